// round 3
// baseline (speedup 1.0000x reference)
#include <cuda_runtime.h>
#include <cstdint>

// Problem constants
#define NB 2
#define NV 25000
#define NTOT (NB * NV)          // 50000 points
#define EDIM 128
#define KNN 16
#define NHEAD 8
#define HDIM 16                  // EDIM / NHEAD

// Scratch: projected tensors + attention output. __device__ globals (no allocs allowed).
__device__ float g_xq[NTOT * EDIM];
__device__ float g_xk[NTOT * EDIM];
__device__ float g_xv[NTOT * EDIM];
__device__ float g_att[NTOT * EDIM];

// ---------------------------------------------------------------------------
// Register-tiled fp32 GEMM: Y[r,f] = sum_e A[r,e] * W[f,e]  (+ optional resid)
// Block: 256 threads computes a 128x128 output tile. K looped in chunks of 32
// through shared memory.
// ---------------------------------------------------------------------------
__device__ __forceinline__ void gemm128_body(
    const float* __restrict__ A, const float* __restrict__ W,
    float* __restrict__ Y, const float* __restrict__ resid, int nrows)
{
    __shared__ float aT[32][132];  // aT[e][r] = A[row0+r][eo+e]
    __shared__ float wT[32][132];  // wT[e][f] = W[f][eo+e]

    const int tid = threadIdx.x;
    const int row0 = blockIdx.x * 128;
    const int tr = tid >> 4;        // 0..15
    const int tc = tid & 15;        // 0..15
    const int rb = tr << 3;         // row base within tile
    const int cb = tc << 3;         // col base within tile

    float acc[8][8];
#pragma unroll
    for (int i = 0; i < 8; i++)
#pragma unroll
        for (int j = 0; j < 8; j++) acc[i][j] = 0.f;

    for (int eo = 0; eo < 128; eo += 32) {
        // Cooperative load: 128 rows x 32 cols of A and of W, transposed into smem.
#pragma unroll
        for (int i = tid; i < 1024; i += 256) {
            int r  = i >> 3;            // 0..127
            int c4 = (i & 7) << 2;      // 0,4,...,28
            int row = row0 + r;
            float4 va = make_float4(0.f, 0.f, 0.f, 0.f);
            if (row < nrows)
                va = *(const float4*)(A + (size_t)row * EDIM + eo + c4);
            aT[c4 + 0][r] = va.x;
            aT[c4 + 1][r] = va.y;
            aT[c4 + 2][r] = va.z;
            aT[c4 + 3][r] = va.w;
            float4 vw = *(const float4*)(W + (size_t)r * EDIM + eo + c4);
            wT[c4 + 0][r] = vw.x;
            wT[c4 + 1][r] = vw.y;
            wT[c4 + 2][r] = vw.z;
            wT[c4 + 3][r] = vw.w;
        }
        __syncthreads();

#pragma unroll
        for (int e = 0; e < 32; e++) {
            float a[8], b[8];
            *(float4*)&a[0] = *(const float4*)&aT[e][rb];
            *(float4*)&a[4] = *(const float4*)&aT[e][rb + 4];
            *(float4*)&b[0] = *(const float4*)&wT[e][cb];
            *(float4*)&b[4] = *(const float4*)&wT[e][cb + 4];
#pragma unroll
            for (int i = 0; i < 8; i++)
#pragma unroll
                for (int j = 0; j < 8; j++)
                    acc[i][j] += a[i] * b[j];
        }
        __syncthreads();
    }

    // Epilogue
#pragma unroll
    for (int i = 0; i < 8; i++) {
        int row = row0 + rb + i;
        if (row >= nrows) break;
        size_t off = (size_t)row * EDIM + cb;
        float4 o0 = make_float4(acc[i][0], acc[i][1], acc[i][2], acc[i][3]);
        float4 o1 = make_float4(acc[i][4], acc[i][5], acc[i][6], acc[i][7]);
        if (resid) {
            float4 r0 = *(const float4*)(resid + off);
            float4 r1 = *(const float4*)(resid + off + 4);
            o0.x += r0.x; o0.y += r0.y; o0.z += r0.z; o0.w += r0.w;
            o1.x += r1.x; o1.y += r1.y; o1.z += r1.z; o1.w += r1.w;
        }
        *(float4*)(Y + off) = o0;
        *(float4*)(Y + off + 4) = o1;
    }
}

__global__ __launch_bounds__(256) void k_proj_qkv(
    const float* __restrict__ x,
    const float* __restrict__ wq,
    const float* __restrict__ wk,
    const float* __restrict__ wv)
{
    const float* W = (blockIdx.y == 0) ? wq : (blockIdx.y == 1) ? wk : wv;
    float* Y       = (blockIdx.y == 0) ? g_xq : (blockIdx.y == 1) ? g_xk : g_xv;
    gemm128_body(x, W, Y, nullptr, NTOT);
}

__global__ __launch_bounds__(256) void k_proj_out(
    const float* __restrict__ x,
    const float* __restrict__ wo,
    float* __restrict__ out)
{
    gemm128_body(g_att, wo, out, x, NTOT);
}

// ---------------------------------------------------------------------------
// Attention kernel: one warp per point, 8 points per 256-thread block.
// Lane t: head h = t>>2, sub-index j = t&3.
//   scores: lane (h,j) computes 4 scores for k in [4j, 4j+4)  (dot over hd=16)
//   softmax: within quads via shfl_xor(1), shfl_xor(2)
//   output: lane (h,j) computes out dims d in [4j, 4j+4), summing 16 neighbors
//   v_in direction trick: out_h = sum_k p_k * XV[g_k]_h  -  XV[center]_h
//   (valid because sum_k p_k == 1)
// ---------------------------------------------------------------------------
__global__ __launch_bounds__(256) void k_attn(const int* __restrict__ idx)
{
    const int warp = threadIdx.x >> 5;
    const int lane = threadIdx.x & 31;
    const int p = blockIdx.x * 8 + warp;   // grid sized so p < NTOT always
    const int b = (p >= NV) ? 1 : 0;

    // Probs are per (head, k): [warps][heads][k]. (Round 2 bug: heads shared slots.)
    __shared__ float s_probs[8][NHEAD][KNN];
    __shared__ int   s_g[8][KNN];

    // Gather neighbor global row indices (idx is int32: JAX default config
    // downcasts the reference's int64 request). Clamp defensively so a dtype
    // surprise shows up as rel_err, not an illegal access.
    if (lane < KNN) {
        int n = idx[(size_t)p * KNN + lane];
        n = (n < 0) ? 0 : (n >= NV ? NV - 1 : n);
        s_g[warp][lane] = b * NV + n;
    }
    __syncwarp();

    const int h = lane >> 2;
    const int j = lane & 3;

    // Load this head's query (16 floats; redundant x4 across the quad, L1-hit)
    float qr[16];
    {
        const float4* qv = (const float4*)(g_xq + (size_t)p * EDIM + (h << 4));
#pragma unroll
        for (int c = 0; c < 4; c++) {
            float4 t = qv[c];
            qr[4 * c + 0] = t.x; qr[4 * c + 1] = t.y;
            qr[4 * c + 2] = t.z; qr[4 * c + 3] = t.w;
        }
    }

    // Scores for k = 4j .. 4j+3
    float sc[4];
#pragma unroll
    for (int i = 0; i < 4; i++) {
        int k = (j << 2) | i;
        int gk = s_g[warp][k];
        const float4* kv = (const float4*)(g_xk + (size_t)gk * EDIM + (h << 4));
        float d = 0.f;
#pragma unroll
        for (int c = 0; c < 4; c++) {
            float4 t = kv[c];
            d += qr[4 * c + 0] * t.x + qr[4 * c + 1] * t.y
               + qr[4 * c + 2] * t.z + qr[4 * c + 3] * t.w;
        }
        sc[i] = d * 0.25f;  // 1/sqrt(hd=16)
    }

    // Softmax over 16 scores spread across the quad (4 lanes x 4 scores)
    float m = fmaxf(fmaxf(sc[0], sc[1]), fmaxf(sc[2], sc[3]));
    m = fmaxf(m, __shfl_xor_sync(0xffffffffu, m, 1));
    m = fmaxf(m, __shfl_xor_sync(0xffffffffu, m, 2));
    float s = 0.f;
#pragma unroll
    for (int i = 0; i < 4; i++) { sc[i] = __expf(sc[i] - m); s += sc[i]; }
    s += __shfl_xor_sync(0xffffffffu, s, 1);
    s += __shfl_xor_sync(0xffffffffu, s, 2);
    float rinv = 1.f / s;
#pragma unroll
    for (int i = 0; i < 4; i++)
        s_probs[warp][h][(j << 2) | i] = sc[i] * rinv;
    __syncwarp();

    // Weighted sum of gathered V rows minus center (sum of probs == 1)
    const size_t doff = (size_t)(h << 4) + (j << 2);
    float4 c = *(const float4*)(g_xv + (size_t)p * EDIM + doff);
    float ax = -c.x, ay = -c.y, az = -c.z, aw = -c.w;
#pragma unroll
    for (int k = 0; k < KNN; k++) {
        float pk = s_probs[warp][h][k];
        int gk = s_g[warp][k];
        float4 v = *(const float4*)(g_xv + (size_t)gk * EDIM + doff);
        ax += pk * v.x; ay += pk * v.y; az += pk * v.z; aw += pk * v.w;
    }
    *(float4*)(g_att + (size_t)p * EDIM + doff) = make_float4(ax, ay, az, aw);
}

// ---------------------------------------------------------------------------
// Launch: 3 kernels, all graph-capturable, no allocations.
// Inputs (metadata order): x[f32 6.4M], idx[i32 800K], w_q, w_k, w_v, w_o [f32 16K each]
// ---------------------------------------------------------------------------
extern "C" void kernel_launch(void* const* d_in, const int* in_sizes, int n_in,
                              void* d_out, int out_size)
{
    const float* x   = (const float*)d_in[0];
    const int*   idx = (const int*)d_in[1];
    const float* wq  = (const float*)d_in[2];
    const float* wk  = (const float*)d_in[3];
    const float* wv  = (const float*)d_in[4];
    const float* wo  = (const float*)d_in[5];
    float*       out = (float*)d_out;

    const int row_blocks = (NTOT + 127) / 128;   // 391

    dim3 gqkv(row_blocks, 3);
    k_proj_qkv<<<gqkv, 256>>>(x, wq, wk, wv);

    k_attn<<<NTOT / 8, 256>>>(idx);              // 6250 blocks, 8 points each

    k_proj_out<<<row_blocks, 256>>>(x, wo, out);
}

// round 4
// speedup vs baseline: 2.0939x; 2.0939x over previous
#include <cuda_runtime.h>
#include <cuda_fp16.h>
#include <cstdint>

// Problem constants
#define NB 2
#define NV 25000
#define NTOT (NB * NV)          // 50000 points
#define EDIM 128
#define KNN 16
#define NHEAD 8

// Scratch (device globals; no allocs allowed).
__device__ float  g_xq[NTOT * EDIM];
__device__ __half g_xk[NTOT * EDIM];
__device__ __half g_xv[NTOT * EDIM];
__device__ float  g_att[NTOT * EDIM];

__device__ __forceinline__ uint32_t f2tf32(float f) {
    uint32_t u;
    asm("cvt.rna.tf32.f32 %0, %1;" : "=r"(u) : "f"(f));
    return u;
}

// ---------------------------------------------------------------------------
// tf32 tensor-core GEMM body: Y[r,n] = sum_e A[r,e] * W[n,e]  (+ optional resid)
// Block: 256 threads (8 warps) -> 128x128 output tile. K chunked by 32 through
// smem. Both A and W tiles stored row-major [128][36] (pad 4): fragment loads
// a0 = As[(rb+gid)*36 + k8+tig] hit banks (4*gid+tig+c)%32 -> conflict-free.
// W rows map directly onto the mma col-major B fragment (B[k][n] = W[n][k]).
// Warp w: rows [32*(w&3), +32), cols [64*(w>>2), +64)  (2 m-tiles x 8 n-tiles).
// ---------------------------------------------------------------------------
__device__ __forceinline__ void tc_gemm_body(
    const float* __restrict__ A, const float* __restrict__ W,
    float* __restrict__ Yf, __half* __restrict__ Yh,
    const float* __restrict__ resid, int nrows)
{
    __shared__ uint32_t As[128 * 36];
    __shared__ uint32_t Ws[128 * 36];

    const int tid  = threadIdx.x;
    const int lane = tid & 31;
    const int w    = tid >> 5;
    const int gid  = lane >> 2;   // 0..7
    const int tig  = lane & 3;    // 0..3
    const int row0 = blockIdx.x * 128;
    const int row_base = (w & 3) << 5;   // 0,32,64,96
    const int col_base = (w >> 2) << 6;  // 0,64

    float acc[2][8][4];
#pragma unroll
    for (int mt = 0; mt < 2; mt++)
#pragma unroll
        for (int t = 0; t < 8; t++)
#pragma unroll
            for (int c = 0; c < 4; c++) acc[mt][t][c] = 0.f;

    for (int ko = 0; ko < EDIM; ko += 32) {
        // Fill: 128 rows x 32 cols of A and W, converted to tf32 bits.
#pragma unroll
        for (int jj = 0; jj < 4; jj++) {
            int i  = tid + jj * 256;        // 0..1023
            int r  = i >> 3;                // 0..127
            int c4 = (i & 7) << 2;          // 0..28
            int row = row0 + r;
            float4 va = make_float4(0.f, 0.f, 0.f, 0.f);
            if (row < nrows)
                va = *(const float4*)(A + (size_t)row * EDIM + ko + c4);
            uint4 ua = make_uint4(f2tf32(va.x), f2tf32(va.y), f2tf32(va.z), f2tf32(va.w));
            *(uint4*)&As[r * 36 + c4] = ua;
            float4 vw = *(const float4*)(W + (size_t)r * EDIM + ko + c4);
            uint4 uw = make_uint4(f2tf32(vw.x), f2tf32(vw.y), f2tf32(vw.z), f2tf32(vw.w));
            *(uint4*)&Ws[r * 36 + c4] = uw;
        }
        __syncthreads();

#pragma unroll
        for (int ks = 0; ks < 4; ks++) {
            const int k8 = ks << 3;
            uint32_t a[2][4], b[8][2];
#pragma unroll
            for (int mt = 0; mt < 2; mt++) {
                int rb = row_base + (mt << 4) + gid;
                a[mt][0] = As[rb * 36 + k8 + tig];
                a[mt][1] = As[(rb + 8) * 36 + k8 + tig];
                a[mt][2] = As[rb * 36 + k8 + 4 + tig];
                a[mt][3] = As[(rb + 8) * 36 + k8 + 4 + tig];
            }
#pragma unroll
            for (int t = 0; t < 8; t++) {
                int nb = col_base + (t << 3) + gid;
                b[t][0] = Ws[nb * 36 + k8 + tig];
                b[t][1] = Ws[nb * 36 + k8 + 4 + tig];
            }
#pragma unroll
            for (int mt = 0; mt < 2; mt++)
#pragma unroll
                for (int t = 0; t < 8; t++) {
                    asm volatile(
                        "mma.sync.aligned.m16n8k8.row.col.f32.tf32.tf32.f32 "
                        "{%0,%1,%2,%3}, {%4,%5,%6,%7}, {%8,%9}, {%0,%1,%2,%3};"
                        : "+f"(acc[mt][t][0]), "+f"(acc[mt][t][1]),
                          "+f"(acc[mt][t][2]), "+f"(acc[mt][t][3])
                        : "r"(a[mt][0]), "r"(a[mt][1]), "r"(a[mt][2]), "r"(a[mt][3]),
                          "r"(b[t][0]), "r"(b[t][1]));
                }
        }
        __syncthreads();
    }

    // Epilogue. c0/c1: row=gid,col=2*tig(,+1); c2/c3: row=gid+8.
#pragma unroll
    for (int mt = 0; mt < 2; mt++) {
        int r0g = row0 + row_base + (mt << 4) + gid;
#pragma unroll
        for (int t = 0; t < 8; t++) {
            int col = col_base + (t << 3) + (tig << 1);
            float2 lo = make_float2(acc[mt][t][0], acc[mt][t][1]);
            float2 hi = make_float2(acc[mt][t][2], acc[mt][t][3]);
            if (r0g < nrows) {
                size_t off = (size_t)r0g * EDIM + col;
                if (resid) { float2 r = *(const float2*)(resid + off); lo.x += r.x; lo.y += r.y; }
                if (Yf) *(float2*)(Yf + off) = lo;
                else    *(__half2*)(Yh + off) = __floats2half2_rn(lo.x, lo.y);
            }
            if (r0g + 8 < nrows) {
                size_t off = (size_t)(r0g + 8) * EDIM + col;
                if (resid) { float2 r = *(const float2*)(resid + off); hi.x += r.x; hi.y += r.y; }
                if (Yf) *(float2*)(Yf + off) = hi;
                else    *(__half2*)(Yh + off) = __floats2half2_rn(hi.x, hi.y);
            }
        }
    }
}

__global__ __launch_bounds__(256) void k_qkv_tc(
    const float* __restrict__ x,
    const float* __restrict__ wq,
    const float* __restrict__ wk,
    const float* __restrict__ wv)
{
    if (blockIdx.y == 0)      tc_gemm_body(x, wq, g_xq, nullptr, nullptr, NTOT);
    else if (blockIdx.y == 1) tc_gemm_body(x, wk, nullptr, g_xk, nullptr, NTOT);
    else                      tc_gemm_body(x, wv, nullptr, g_xv, nullptr, NTOT);
}

__global__ __launch_bounds__(256) void k_out_tc(
    const float* __restrict__ x,
    const float* __restrict__ wo,
    float* __restrict__ out)
{
    tc_gemm_body(g_att, wo, out, nullptr, x, NTOT);
}

// ---------------------------------------------------------------------------
// Attention kernel: one warp per point, 8 points per 256-thread block.
// Lane t: head h = t>>2, sub-index j = t&3. K/V gathered from fp16 scratch.
//   out_h = sum_k p_k * XV[g_k]_h - XV[center]_h   (sum_k p_k == 1)
// ---------------------------------------------------------------------------
__global__ __launch_bounds__(256) void k_attn(const int* __restrict__ idx)
{
    const int warp = threadIdx.x >> 5;
    const int lane = threadIdx.x & 31;
    const int p = blockIdx.x * 8 + warp;
    const int b = (p >= NV) ? 1 : 0;

    __shared__ float s_probs[8][NHEAD][KNN];
    __shared__ int   s_g[8][KNN];

    if (lane < KNN) {
        int n = idx[(size_t)p * KNN + lane];
        n = (n < 0) ? 0 : (n >= NV ? NV - 1 : n);
        s_g[warp][lane] = b * NV + n;
    }
    __syncwarp();

    const int h = lane >> 2;
    const int j = lane & 3;

    // Query head-slice (fp32)
    float qr[16];
    {
        const float4* qv = (const float4*)(g_xq + (size_t)p * EDIM + (h << 4));
#pragma unroll
        for (int c = 0; c < 4; c++) {
            float4 t = qv[c];
            qr[4 * c + 0] = t.x; qr[4 * c + 1] = t.y;
            qr[4 * c + 2] = t.z; qr[4 * c + 3] = t.w;
        }
    }

    // Scores for k = 4j .. 4j+3 (K rows in fp16: 16 halfs = two uint4)
    float sc[4];
#pragma unroll
    for (int i = 0; i < 4; i++) {
        int k = (j << 2) | i;
        int gk = s_g[warp][k];
        const uint4* kp = (const uint4*)(g_xk + (size_t)gk * EDIM + (h << 4));
        uint4 u0 = kp[0];
        uint4 u1 = kp[1];
        const __half2* h0 = (const __half2*)&u0;
        const __half2* h1 = (const __half2*)&u1;
        float d = 0.f;
#pragma unroll
        for (int c = 0; c < 4; c++) {
            float2 f0 = __half22float2(h0[c]);
            float2 f1 = __half22float2(h1[c]);
            d += qr[2 * c + 0] * f0.x + qr[2 * c + 1] * f0.y
               + qr[8 + 2 * c + 0] * f1.x + qr[8 + 2 * c + 1] * f1.y;
        }
        sc[i] = d * 0.25f;  // 1/sqrt(hd=16)
    }

    // Softmax over 16 scores across the quad
    float m = fmaxf(fmaxf(sc[0], sc[1]), fmaxf(sc[2], sc[3]));
    m = fmaxf(m, __shfl_xor_sync(0xffffffffu, m, 1));
    m = fmaxf(m, __shfl_xor_sync(0xffffffffu, m, 2));
    float s = 0.f;
#pragma unroll
    for (int i = 0; i < 4; i++) { sc[i] = __expf(sc[i] - m); s += sc[i]; }
    s += __shfl_xor_sync(0xffffffffu, s, 1);
    s += __shfl_xor_sync(0xffffffffu, s, 2);
    float rinv = 1.f / s;
#pragma unroll
    for (int i = 0; i < 4; i++)
        s_probs[warp][h][(j << 2) | i] = sc[i] * rinv;
    __syncwarp();

    // Weighted sum of gathered fp16 V rows minus center
    const size_t doff = (size_t)(h << 4) + (j << 2);
    float ax, ay, az, aw;
    {
        uint2 raw = *(const uint2*)(g_xv + (size_t)p * EDIM + doff);
        __half2 c0 = *(__half2*)&raw.x, c1 = *(__half2*)&raw.y;
        float2 f0 = __half22float2(c0), f1 = __half22float2(c1);
        ax = -f0.x; ay = -f0.y; az = -f1.x; aw = -f1.y;
    }
#pragma unroll
    for (int k = 0; k < KNN; k++) {
        float pk = s_probs[warp][h][k];
        int gk = s_g[warp][k];
        uint2 raw = *(const uint2*)(g_xv + (size_t)gk * EDIM + doff);
        __half2 v0 = *(__half2*)&raw.x, v1 = *(__half2*)&raw.y;
        float2 f0 = __half22float2(v0), f1 = __half22float2(v1);
        ax += pk * f0.x; ay += pk * f0.y; az += pk * f1.x; aw += pk * f1.y;
    }
    *(float4*)(g_att + (size_t)p * EDIM + doff) = make_float4(ax, ay, az, aw);
}

// ---------------------------------------------------------------------------
// Inputs (metadata order): x[f32], idx[i32], w_q, w_k, w_v, w_o [f32]
// ---------------------------------------------------------------------------
extern "C" void kernel_launch(void* const* d_in, const int* in_sizes, int n_in,
                              void* d_out, int out_size)
{
    const float* x   = (const float*)d_in[0];
    const int*   idx = (const int*)d_in[1];
    const float* wq  = (const float*)d_in[2];
    const float* wk  = (const float*)d_in[3];
    const float* wv  = (const float*)d_in[4];
    const float* wo  = (const float*)d_in[5];
    float*       out = (float*)d_out;

    const int row_blocks = (NTOT + 127) / 128;   // 391

    dim3 gqkv(row_blocks, 3);
    k_qkv_tc<<<gqkv, 256>>>(x, wq, wk, wv);

    k_attn<<<NTOT / 8, 256>>>(idx);              // 6250 blocks, 8 points each

    k_out_tc<<<row_blocks, 256>>>(x, wo, out);
}

// round 5
// speedup vs baseline: 2.4630x; 1.1763x over previous
#include <cuda_runtime.h>
#include <cuda_fp16.h>
#include <cstdint>

// Problem constants
#define NB 2
#define NV 25000
#define NTOT (NB * NV)          // 50000 points
#define EDIM 128
#define KNN 16
#define NHEAD 8

// Scratch (device globals; no allocs allowed).
__device__ float  g_xq[NTOT * EDIM];
__device__ __half g_xk[NTOT * EDIM];
__device__ __half g_xv[NTOT * EDIM];
__device__ float  g_att[NTOT * EDIM];

// ---------------------------------------------------------------------------
// fp16 tensor-core GEMM body (fp32 accumulate):
//   Y[r,n] = sum_e A[r,e] * W[n,e]  (+ optional resid)
// Block: 256 threads (8 warps) -> 128x128 tile. K chunked by 64 through smem.
// Tiles stored fp16 row-major, row stride 72 halfs (144 B = 9*16B: ldmatrix-
// aligned, 36-bank stride -> conflict-free 8-row reads).
// W rows (n-major, k-contiguous) map directly onto the mma col.B fragment via
// non-transposed ldmatrix. Warp w: rows [32*(w&3),+32), cols [64*(w>>2),+64).
// Per warp-k16: 2 ldmatrix.x4 (A) + 4 ldmatrix.x4 (B) + 16 HMMA m16n8k16.
// ---------------------------------------------------------------------------
#define LDROW 72

__device__ __forceinline__ void tc_gemm_body(
    const float* __restrict__ A, const float* __restrict__ W,
    float* __restrict__ Yf, __half* __restrict__ Yh,
    const float* __restrict__ resid, int nrows)
{
    __shared__ __half As[128 * LDROW];
    __shared__ __half Ws[128 * LDROW];

    const int tid  = threadIdx.x;
    const int lane = tid & 31;
    const int w    = tid >> 5;
    const int gid  = lane >> 2;   // 0..7
    const int tig  = lane & 3;    // 0..3
    const int row0 = blockIdx.x * 128;
    const int row_base = (w & 3) << 5;   // 0,32,64,96
    const int col_base = (w >> 2) << 6;  // 0,64

    // ldmatrix lane->address mapping
    const int l7 = lane & 7;
    const int a_row_sel = ((lane >> 3) & 1) << 3;  // +8 rows for m1,m3
    const int a_k_sel   = (lane >> 4) << 3;        // +8 k    for m2,m3
    const int b_row_sel = (lane >> 4) << 3;        // +8 n    for m2,m3
    const int b_k_sel   = ((lane >> 3) & 1) << 3;  // +8 k    for m1,m3

    uint32_t a_addr[2], b_addr[4];
#pragma unroll
    for (int mt = 0; mt < 2; mt++) {
        int r = row_base + (mt << 4) + a_row_sel + l7;
        a_addr[mt] = (uint32_t)__cvta_generic_to_shared(&As[r * LDROW + a_k_sel]);
    }
#pragma unroll
    for (int tp = 0; tp < 4; tp++) {
        int r = col_base + (tp << 4) + b_row_sel + l7;
        b_addr[tp] = (uint32_t)__cvta_generic_to_shared(&Ws[r * LDROW + b_k_sel]);
    }

    float acc[2][8][4];
#pragma unroll
    for (int mt = 0; mt < 2; mt++)
#pragma unroll
        for (int t = 0; t < 8; t++)
#pragma unroll
            for (int c = 0; c < 4; c++) acc[mt][t][c] = 0.f;

    for (int ko = 0; ko < EDIM; ko += 64) {
        // Fill: 128 rows x 64 cols of A and W, converted fp32 -> fp16.
#pragma unroll
        for (int jj = 0; jj < 8; jj++) {
            int i  = tid + (jj << 8);       // 0..2047
            int r  = i >> 4;                // 0..127
            int c4 = (i & 15) << 2;         // 0..60
            int row = row0 + r;
            float4 va = make_float4(0.f, 0.f, 0.f, 0.f);
            if (row < nrows)
                va = *(const float4*)(A + (size_t)row * EDIM + ko + c4);
            __half2 a0 = __floats2half2_rn(va.x, va.y);
            __half2 a1 = __floats2half2_rn(va.z, va.w);
            *(uint2*)&As[r * LDROW + c4] =
                make_uint2(*(uint32_t*)&a0, *(uint32_t*)&a1);
            float4 vw = *(const float4*)(W + (size_t)r * EDIM + ko + c4);
            __half2 w0 = __floats2half2_rn(vw.x, vw.y);
            __half2 w1 = __floats2half2_rn(vw.z, vw.w);
            *(uint2*)&Ws[r * LDROW + c4] =
                make_uint2(*(uint32_t*)&w0, *(uint32_t*)&w1);
        }
        __syncthreads();

#pragma unroll
        for (int ks = 0; ks < 4; ks++) {
            const uint32_t kofs = ks * 32;  // 16 halfs * 2B
            uint32_t a[2][4], b[8][2];
#pragma unroll
            for (int mt = 0; mt < 2; mt++)
                asm volatile(
                    "ldmatrix.sync.aligned.m8n8.x4.shared.b16 {%0,%1,%2,%3}, [%4];"
                    : "=r"(a[mt][0]), "=r"(a[mt][1]), "=r"(a[mt][2]), "=r"(a[mt][3])
                    : "r"(a_addr[mt] + kofs));
#pragma unroll
            for (int tp = 0; tp < 4; tp++)
                asm volatile(
                    "ldmatrix.sync.aligned.m8n8.x4.shared.b16 {%0,%1,%2,%3}, [%4];"
                    : "=r"(b[2 * tp][0]), "=r"(b[2 * tp][1]),
                      "=r"(b[2 * tp + 1][0]), "=r"(b[2 * tp + 1][1])
                    : "r"(b_addr[tp] + kofs));
#pragma unroll
            for (int mt = 0; mt < 2; mt++)
#pragma unroll
                for (int t = 0; t < 8; t++)
                    asm volatile(
                        "mma.sync.aligned.m16n8k16.row.col.f32.f16.f16.f32 "
                        "{%0,%1,%2,%3}, {%4,%5,%6,%7}, {%8,%9}, {%0,%1,%2,%3};"
                        : "+f"(acc[mt][t][0]), "+f"(acc[mt][t][1]),
                          "+f"(acc[mt][t][2]), "+f"(acc[mt][t][3])
                        : "r"(a[mt][0]), "r"(a[mt][1]), "r"(a[mt][2]), "r"(a[mt][3]),
                          "r"(b[t][0]), "r"(b[t][1]));
        }
        __syncthreads();
    }

    // Epilogue. c0/c1: row=gid, col=2*tig(,+1); c2/c3: row=gid+8.
#pragma unroll
    for (int mt = 0; mt < 2; mt++) {
        int r0g = row0 + row_base + (mt << 4) + gid;
#pragma unroll
        for (int t = 0; t < 8; t++) {
            int col = col_base + (t << 3) + (tig << 1);
            float2 lo = make_float2(acc[mt][t][0], acc[mt][t][1]);
            float2 hi = make_float2(acc[mt][t][2], acc[mt][t][3]);
            if (r0g < nrows) {
                size_t off = (size_t)r0g * EDIM + col;
                if (resid) { float2 r = *(const float2*)(resid + off); lo.x += r.x; lo.y += r.y; }
                if (Yf) *(float2*)(Yf + off) = lo;
                else    *(__half2*)(Yh + off) = __floats2half2_rn(lo.x, lo.y);
            }
            if (r0g + 8 < nrows) {
                size_t off = (size_t)(r0g + 8) * EDIM + col;
                if (resid) { float2 r = *(const float2*)(resid + off); hi.x += r.x; hi.y += r.y; }
                if (Yf) *(float2*)(Yf + off) = hi;
                else    *(__half2*)(Yh + off) = __floats2half2_rn(hi.x, hi.y);
            }
        }
    }
}

__global__ __launch_bounds__(256) void k_qkv_tc(
    const float* __restrict__ x,
    const float* __restrict__ wq,
    const float* __restrict__ wk,
    const float* __restrict__ wv)
{
    if (blockIdx.y == 0)      tc_gemm_body(x, wq, g_xq, nullptr, nullptr, NTOT);
    else if (blockIdx.y == 1) tc_gemm_body(x, wk, nullptr, g_xk, nullptr, NTOT);
    else                      tc_gemm_body(x, wv, nullptr, g_xv, nullptr, NTOT);
}

__global__ __launch_bounds__(256) void k_out_tc(
    const float* __restrict__ x,
    const float* __restrict__ wo,
    float* __restrict__ out)
{
    tc_gemm_body(g_att, wo, out, nullptr, x, NTOT);
}

// ---------------------------------------------------------------------------
// Attention kernel: one warp per point, 8 points per 256-thread block.
// Lane t: head h = t>>2, sub-index j = t&3. K/V gathered from fp16 scratch.
//   out_h = sum_k p_k * XV[g_k]_h - XV[center]_h   (sum_k p_k == 1)
// ---------------------------------------------------------------------------
__global__ __launch_bounds__(256) void k_attn(const int* __restrict__ idx)
{
    const int warp = threadIdx.x >> 5;
    const int lane = threadIdx.x & 31;
    const int p = blockIdx.x * 8 + warp;
    const int b = (p >= NV) ? 1 : 0;

    __shared__ float s_probs[8][NHEAD][KNN];
    __shared__ int   s_g[8][KNN];

    if (lane < KNN) {
        int n = idx[(size_t)p * KNN + lane];
        n = (n < 0) ? 0 : (n >= NV ? NV - 1 : n);
        s_g[warp][lane] = b * NV + n;
    }
    __syncwarp();

    const int h = lane >> 2;
    const int j = lane & 3;

    // Query head-slice (fp32)
    float qr[16];
    {
        const float4* qv = (const float4*)(g_xq + (size_t)p * EDIM + (h << 4));
#pragma unroll
        for (int c = 0; c < 4; c++) {
            float4 t = qv[c];
            qr[4 * c + 0] = t.x; qr[4 * c + 1] = t.y;
            qr[4 * c + 2] = t.z; qr[4 * c + 3] = t.w;
        }
    }

    // Scores for k = 4j .. 4j+3 (K rows in fp16: 16 halfs = two uint4)
    float sc[4];
#pragma unroll
    for (int i = 0; i < 4; i++) {
        int k = (j << 2) | i;
        int gk = s_g[warp][k];
        const uint4* kp = (const uint4*)(g_xk + (size_t)gk * EDIM + (h << 4));
        uint4 u0 = kp[0];
        uint4 u1 = kp[1];
        const __half2* h0 = (const __half2*)&u0;
        const __half2* h1 = (const __half2*)&u1;
        float d = 0.f;
#pragma unroll
        for (int c = 0; c < 4; c++) {
            float2 f0 = __half22float2(h0[c]);
            float2 f1 = __half22float2(h1[c]);
            d += qr[2 * c + 0] * f0.x + qr[2 * c + 1] * f0.y
               + qr[8 + 2 * c + 0] * f1.x + qr[8 + 2 * c + 1] * f1.y;
        }
        sc[i] = d * 0.25f;  // 1/sqrt(hd=16)
    }

    // Softmax over 16 scores across the quad
    float m = fmaxf(fmaxf(sc[0], sc[1]), fmaxf(sc[2], sc[3]));
    m = fmaxf(m, __shfl_xor_sync(0xffffffffu, m, 1));
    m = fmaxf(m, __shfl_xor_sync(0xffffffffu, m, 2));
    float s = 0.f;
#pragma unroll
    for (int i = 0; i < 4; i++) { sc[i] = __expf(sc[i] - m); s += sc[i]; }
    s += __shfl_xor_sync(0xffffffffu, s, 1);
    s += __shfl_xor_sync(0xffffffffu, s, 2);
    float rinv = 1.f / s;
#pragma unroll
    for (int i = 0; i < 4; i++)
        s_probs[warp][h][(j << 2) | i] = sc[i] * rinv;
    __syncwarp();

    // Weighted sum of gathered fp16 V rows minus center
    const size_t doff = (size_t)(h << 4) + (j << 2);
    float ax, ay, az, aw;
    {
        uint2 raw = *(const uint2*)(g_xv + (size_t)p * EDIM + doff);
        __half2 c0 = *(__half2*)&raw.x, c1 = *(__half2*)&raw.y;
        float2 f0 = __half22float2(c0), f1 = __half22float2(c1);
        ax = -f0.x; ay = -f0.y; az = -f1.x; aw = -f1.y;
    }
#pragma unroll
    for (int k = 0; k < KNN; k++) {
        float pk = s_probs[warp][h][k];
        int gk = s_g[warp][k];
        uint2 raw = *(const uint2*)(g_xv + (size_t)gk * EDIM + doff);
        __half2 v0 = *(__half2*)&raw.x, v1 = *(__half2*)&raw.y;
        float2 f0 = __half22float2(v0), f1 = __half22float2(v1);
        ax += pk * f0.x; ay += pk * f0.y; az += pk * f1.x; aw += pk * f1.y;
    }
    *(float4*)(g_att + (size_t)p * EDIM + doff) = make_float4(ax, ay, az, aw);
}

// ---------------------------------------------------------------------------
// Inputs (metadata order): x[f32], idx[i32], w_q, w_k, w_v, w_o [f32]
// ---------------------------------------------------------------------------
extern "C" void kernel_launch(void* const* d_in, const int* in_sizes, int n_in,
                              void* d_out, int out_size)
{
    const float* x   = (const float*)d_in[0];
    const int*   idx = (const int*)d_in[1];
    const float* wq  = (const float*)d_in[2];
    const float* wk  = (const float*)d_in[3];
    const float* wv  = (const float*)d_in[4];
    const float* wo  = (const float*)d_in[5];
    float*       out = (float*)d_out;

    const int row_blocks = (NTOT + 127) / 128;   // 391

    dim3 gqkv(row_blocks, 3);
    k_qkv_tc<<<gqkv, 256>>>(x, wq, wk, wv);

    k_attn<<<NTOT / 8, 256>>>(idx);              // 6250 blocks, 8 points each

    k_out_tc<<<row_blocks, 256>>>(x, wo, out);
}

// round 7
// speedup vs baseline: 2.9546x; 1.1996x over previous
#include <cuda_runtime.h>
#include <cuda_fp16.h>
#include <cstdint>

// Problem constants
#define NB 2
#define NV 25000
#define NTOT (NB * NV)          // 50000 points
#define EDIM 128
#define KNN 16
#define NHEAD 8

#define LDROW 72                        // halfs per smem row (144B = 9*16B)
#define CHUNK_HALFS (128 * LDROW)       // one 128x64 chunk
#define CHUNK_BYTES (CHUNK_HALFS * 2)   // 18432
#define SMEM_BYTES (4 * CHUNK_BYTES)    // 73728: A0,A1,W0,W1

// Scratch (device globals; no allocs allowed). All fp16.
__device__ __half g_xh [NTOT * EDIM];       // x converted to fp16
__device__ __half g_wh [4 * EDIM * EDIM];   // wq,wk,wv,wo in fp16
__device__ __half g_xq [NTOT * EDIM];
__device__ __half g_xk [NTOT * EDIM];
__device__ __half g_xv [NTOT * EDIM];
__device__ __half g_att[NTOT * EDIM];

// ---------------------------------------------------------------------------
// cp.async helpers
// ---------------------------------------------------------------------------
__device__ __forceinline__ void cp16(uint32_t dst, const void* src, bool pred) {
    asm volatile("cp.async.cg.shared.global [%0], [%1], 16, %2;"
                 :: "r"(dst), "l"(src), "r"(pred ? 16 : 0));
}
#define CP_COMMIT() asm volatile("cp.async.commit_group;")
#define CP_WAIT(n)  asm volatile("cp.async.wait_group %0;" :: "n"(n))

// Copy a 128-row x 64-col fp16 chunk (src stride EDIM) into an smem chunk.
__device__ __forceinline__ void fill_chunk(
    uint32_t sbase, const __half* __restrict__ src,
    int row0, int ko, int nrows, int tid)
{
#pragma unroll
    for (int jj = 0; jj < 4; jj++) {
        int u  = tid + (jj << 8);           // 0..1023
        int r  = u >> 3;
        int c8 = (u & 7) << 3;              // 0..56
        uint32_t dst = sbase + (uint32_t)(r * LDROW + c8) * 2;
        const __half* s = src + (size_t)(row0 + r) * EDIM + ko + c8;
        cp16(dst, s, row0 + r < nrows);
    }
}

// ---------------------------------------------------------------------------
// Pre-convert: x -> g_xh, weights -> g_wh. Pure streaming.
//   blocks [0,6250): x (1024 floats each);  blocks [6250,6314): weights.
// ---------------------------------------------------------------------------
__global__ __launch_bounds__(256) void k_convert(
    const float* __restrict__ x,
    const float* __restrict__ wq, const float* __restrict__ wk,
    const float* __restrict__ wv, const float* __restrict__ wo)
{
    int bid = blockIdx.x;
    int t = threadIdx.x;
    const float* src;
    __half* dst;
    size_t off;
    if (bid < 6250) {
        off = (size_t)bid * 1024 + t * 4;
        src = x; dst = g_xh;
    } else {
        int wb = bid - 6250;                 // 0..63, 16 blocks per weight
        int wsel = wb >> 4;
        src = (wsel == 0) ? wq : (wsel == 1) ? wk : (wsel == 2) ? wv : wo;
        dst = g_wh + wsel * (EDIM * EDIM);
        off = (size_t)(wb & 15) * 1024 + t * 4;
    }
    float4 v = *(const float4*)(src + off);
    __half2 h0 = __floats2half2_rn(v.x, v.y);
    __half2 h1 = __floats2half2_rn(v.z, v.w);
    *(uint2*)(dst + off) = make_uint2(*(uint32_t*)&h0, *(uint32_t*)&h1);
}

// ---------------------------------------------------------------------------
// fp16 tensor-core GEMM (fp32 accumulate): Y[r,n] = sum_e A[r,e]*W[n,e] (+resid)
// 256 threads -> 128x128 tile, K in two 64-chunks, all 4 chunk fills issued
// via cp.async before the first MMA. Warp w: rows [32*(w&3),+32),
// cols [64*(w>>2),+64). Per warp-k16: 6 ldmatrix.x4 + 16 HMMA m16n8k16.
// ---------------------------------------------------------------------------
__device__ __forceinline__ void tc_gemm16(
    const __half* __restrict__ Asrc, const __half* __restrict__ Wsrc,
    __half* __restrict__ Yh, float* __restrict__ Yf,
    const float* __restrict__ resid)
{
    extern __shared__ __half sm[];
    uint32_t sbase = (uint32_t)__cvta_generic_to_shared(sm);
    uint32_t Ab[2] = { sbase,                   sbase + CHUNK_BYTES };
    uint32_t Wb[2] = { sbase + 2 * CHUNK_BYTES, sbase + 3 * CHUNK_BYTES };

    const int tid  = threadIdx.x;
    const int lane = tid & 31;
    const int w    = tid >> 5;
    const int gid  = lane >> 2;
    const int tig  = lane & 3;
    const int row0 = blockIdx.x * 128;
    const int row_base = (w & 3) << 5;
    const int col_base = (w >> 2) << 6;

    // Prologue: issue all fills (group0 = step0 chunks, group1 = step1 chunks)
    fill_chunk(Ab[0], Asrc, row0, 0, NTOT, tid);
    fill_chunk(Wb[0], Wsrc, 0, 0, 128, tid);
    CP_COMMIT();
    fill_chunk(Ab[1], Asrc, row0, 64, NTOT, tid);
    fill_chunk(Wb[1], Wsrc, 0, 64, 128, tid);
    CP_COMMIT();

    // ldmatrix lane->offset mapping (byte offsets within a chunk)
    const int l7 = lane & 7;
    const int a_row_sel = ((lane >> 3) & 1) << 3;
    const int a_k_sel   = (lane >> 4) << 3;
    const int b_row_sel = (lane >> 4) << 3;
    const int b_k_sel   = ((lane >> 3) & 1) << 3;
    uint32_t a_off[2], b_off[4];
#pragma unroll
    for (int mt = 0; mt < 2; mt++)
        a_off[mt] = (uint32_t)((row_base + (mt << 4) + a_row_sel + l7) * LDROW + a_k_sel) * 2;
#pragma unroll
    for (int tp = 0; tp < 4; tp++)
        b_off[tp] = (uint32_t)((col_base + (tp << 4) + b_row_sel + l7) * LDROW + b_k_sel) * 2;

    float acc[2][8][4];
#pragma unroll
    for (int mt = 0; mt < 2; mt++)
#pragma unroll
        for (int t = 0; t < 8; t++)
#pragma unroll
            for (int c = 0; c < 4; c++) acc[mt][t][c] = 0.f;

#pragma unroll
    for (int step = 0; step < 2; step++) {
        if (step == 0) { CP_WAIT(1); } else { CP_WAIT(0); }
        __syncthreads();
        const uint32_t Ac = Ab[step], Wc = Wb[step];
#pragma unroll
        for (int ks = 0; ks < 4; ks++) {
            const uint32_t kofs = ks * 32;  // 16 halfs
            uint32_t a[2][4], b[8][2];
#pragma unroll
            for (int mt = 0; mt < 2; mt++)
                asm volatile(
                    "ldmatrix.sync.aligned.m8n8.x4.shared.b16 {%0,%1,%2,%3}, [%4];"
                    : "=r"(a[mt][0]), "=r"(a[mt][1]), "=r"(a[mt][2]), "=r"(a[mt][3])
                    : "r"(Ac + a_off[mt] + kofs));
#pragma unroll
            for (int tp = 0; tp < 4; tp++)
                asm volatile(
                    "ldmatrix.sync.aligned.m8n8.x4.shared.b16 {%0,%1,%2,%3}, [%4];"
                    : "=r"(b[2 * tp][0]), "=r"(b[2 * tp][1]),
                      "=r"(b[2 * tp + 1][0]), "=r"(b[2 * tp + 1][1])
                    : "r"(Wc + b_off[tp] + kofs));
#pragma unroll
            for (int mt = 0; mt < 2; mt++)
#pragma unroll
                for (int t = 0; t < 8; t++)
                    asm volatile(
                        "mma.sync.aligned.m16n8k16.row.col.f32.f16.f16.f32 "
                        "{%0,%1,%2,%3}, {%4,%5,%6,%7}, {%8,%9}, {%0,%1,%2,%3};"
                        : "+f"(acc[mt][t][0]), "+f"(acc[mt][t][1]),
                          "+f"(acc[mt][t][2]), "+f"(acc[mt][t][3])
                        : "r"(a[mt][0]), "r"(a[mt][1]), "r"(a[mt][2]), "r"(a[mt][3]),
                          "r"(b[t][0]), "r"(b[t][1]));
        }
        // no trailing sync: step buffers are never reused
    }

    // Epilogue. c0/c1: row=gid, col=2*tig(,+1); c2/c3: row=gid+8.
#pragma unroll
    for (int mt = 0; mt < 2; mt++) {
        int r0g = row0 + row_base + (mt << 4) + gid;
#pragma unroll
        for (int t = 0; t < 8; t++) {
            int col = col_base + (t << 3) + (tig << 1);
            float2 lo = make_float2(acc[mt][t][0], acc[mt][t][1]);
            float2 hi = make_float2(acc[mt][t][2], acc[mt][t][3]);
            if (r0g < NTOT) {
                size_t off = (size_t)r0g * EDIM + col;
                if (Yf) {
                    float2 r = *(const float2*)(resid + off);
                    lo.x += r.x; lo.y += r.y;
                    *(float2*)(Yf + off) = lo;
                } else {
                    __half2 hv = __floats2half2_rn(lo.x, lo.y);
                    *(uint32_t*)(Yh + off) = *(uint32_t*)&hv;
                }
            }
            if (r0g + 8 < NTOT) {
                size_t off = (size_t)(r0g + 8) * EDIM + col;
                if (Yf) {
                    float2 r = *(const float2*)(resid + off);
                    hi.x += r.x; hi.y += r.y;
                    *(float2*)(Yf + off) = hi;
                } else {
                    __half2 hv = __floats2half2_rn(hi.x, hi.y);
                    *(uint32_t*)(Yh + off) = *(uint32_t*)&hv;
                }
            }
        }
    }
}

__global__ __launch_bounds__(256) void k_qkv_f()
{
    int wsel = blockIdx.y;
    __half* Y = (wsel == 0) ? g_xq : (wsel == 1) ? g_xk : g_xv;
    tc_gemm16(g_xh, g_wh + wsel * (EDIM * EDIM), Y, nullptr, nullptr);
}

__global__ __launch_bounds__(256) void k_out_f(
    const float* __restrict__ x, float* __restrict__ out)
{
    tc_gemm16(g_att, g_wh + 3 * (EDIM * EDIM), nullptr, out, x);
}

// ---------------------------------------------------------------------------
// Attention: one warp per point, 8 points/block. All operands fp16 scratch.
// Lane t: head h=t>>2, j=t&3.  out_h = sum_k p_k*XV[g_k]_h - XV[center]_h
// NOTE: a head slice is 16 halfs = 32 bytes = TWO uint4 loads (round-6 NaN
// bug was loading only one and reading past it).
// ---------------------------------------------------------------------------
__global__ __launch_bounds__(256) void k_attn(const int* __restrict__ idx)
{
    const int warp = threadIdx.x >> 5;
    const int lane = threadIdx.x & 31;
    const int p = blockIdx.x * 8 + warp;
    const int b = (p >= NV) ? 1 : 0;

    __shared__ float s_probs[8][NHEAD][KNN];
    __shared__ int   s_g[8][KNN];

    if (lane < KNN) {
        int n = idx[(size_t)p * KNN + lane];
        n = (n < 0) ? 0 : (n >= NV ? NV - 1 : n);
        s_g[warp][lane] = b * NV + n;
    }
    __syncwarp();

    const int h = lane >> 2;
    const int j = lane & 3;

    // Query head-slice: 16 halfs = two uint4
    float qr[16];
    {
        const uint4* qp = (const uint4*)(g_xq + (size_t)p * EDIM + (h << 4));
        uint4 qu[2] = { qp[0], qp[1] };
        const __half2* qh = (const __half2*)qu;
#pragma unroll
        for (int c = 0; c < 8; c++) {
            float2 f = __half22float2(qh[c]);
            qr[2 * c] = f.x; qr[2 * c + 1] = f.y;
        }
    }

    // Scores for k = 4j .. 4j+3 (K head slice: 16 halfs = two uint4)
    float sc[4];
#pragma unroll
    for (int i = 0; i < 4; i++) {
        int k = (j << 2) | i;
        int gk = s_g[warp][k];
        const uint4* kp = (const uint4*)(g_xk + (size_t)gk * EDIM + (h << 4));
        uint4 ku[2] = { kp[0], kp[1] };
        const __half2* kh = (const __half2*)ku;
        float d = 0.f;
#pragma unroll
        for (int c = 0; c < 8; c++) {
            float2 f = __half22float2(kh[c]);
            d += qr[2 * c] * f.x + qr[2 * c + 1] * f.y;
        }
        sc[i] = d * 0.25f;  // 1/sqrt(hd=16)
    }

    // Softmax over 16 scores across the quad
    float m = fmaxf(fmaxf(sc[0], sc[1]), fmaxf(sc[2], sc[3]));
    m = fmaxf(m, __shfl_xor_sync(0xffffffffu, m, 1));
    m = fmaxf(m, __shfl_xor_sync(0xffffffffu, m, 2));
    float s = 0.f;
#pragma unroll
    for (int i = 0; i < 4; i++) { sc[i] = __expf(sc[i] - m); s += sc[i]; }
    s += __shfl_xor_sync(0xffffffffu, s, 1);
    s += __shfl_xor_sync(0xffffffffu, s, 2);
    float rinv = 1.f / s;
#pragma unroll
    for (int i = 0; i < 4; i++)
        s_probs[warp][h][(j << 2) | i] = sc[i] * rinv;
    __syncwarp();

    // Weighted sum of gathered fp16 V rows minus center (4 halfs per lane)
    const size_t doff = (size_t)(h << 4) + (j << 2);
    float ax, ay, az, aw;
    {
        uint2 raw = *(const uint2*)(g_xv + (size_t)p * EDIM + doff);
        float2 f0 = __half22float2(*(__half2*)&raw.x);
        float2 f1 = __half22float2(*(__half2*)&raw.y);
        ax = -f0.x; ay = -f0.y; az = -f1.x; aw = -f1.y;
    }
#pragma unroll
    for (int k = 0; k < KNN; k++) {
        float pk = s_probs[warp][h][k];
        int gk = s_g[warp][k];
        uint2 raw = *(const uint2*)(g_xv + (size_t)gk * EDIM + doff);
        float2 f0 = __half22float2(*(__half2*)&raw.x);
        float2 f1 = __half22float2(*(__half2*)&raw.y);
        ax += pk * f0.x; ay += pk * f0.y; az += pk * f1.x; aw += pk * f1.y;
    }
    __half2 o0 = __floats2half2_rn(ax, ay);
    __half2 o1 = __floats2half2_rn(az, aw);
    *(uint2*)(g_att + (size_t)p * EDIM + doff) =
        make_uint2(*(uint32_t*)&o0, *(uint32_t*)&o1);
}

// ---------------------------------------------------------------------------
// Inputs (metadata order): x[f32], idx[i32], w_q, w_k, w_v, w_o [f32]
// ---------------------------------------------------------------------------
extern "C" void kernel_launch(void* const* d_in, const int* in_sizes, int n_in,
                              void* d_out, int out_size)
{
    const float* x   = (const float*)d_in[0];
    const int*   idx = (const int*)d_in[1];
    const float* wq  = (const float*)d_in[2];
    const float* wk  = (const float*)d_in[3];
    const float* wv  = (const float*)d_in[4];
    const float* wo  = (const float*)d_in[5];
    float*       out = (float*)d_out;

    cudaFuncSetAttribute(k_qkv_f, cudaFuncAttributeMaxDynamicSharedMemorySize, SMEM_BYTES);
    cudaFuncSetAttribute(k_out_f, cudaFuncAttributeMaxDynamicSharedMemorySize, SMEM_BYTES);

    const int row_blocks = (NTOT + 127) / 128;   // 391

    k_convert<<<6250 + 64, 256>>>(x, wq, wk, wv, wo);

    dim3 gqkv(row_blocks, 3);
    k_qkv_f<<<gqkv, 256, SMEM_BYTES>>>();

    k_attn<<<NTOT / 8, 256>>>(idx);

    k_out_f<<<row_blocks, 256, SMEM_BYTES>>>(x, out);
}